// round 1
// baseline (speedup 1.0000x reference)
#include <cuda_runtime.h>

#define B_    16
#define C_    256
#define HW_   3136
#define Wim_  56
#define CI_   32
#define CG_   64
#define NP_   784
#define WP_   28
#define CCAT_ 128

// ---------------- scratch (static device globals; no allocation) ----------------
__device__ float d_wcat[CCAT_ * C_];
__device__ float d_bcat[CCAT_];
__device__ float d_a1[C_], d_b1[C_];
__device__ float d_a2[CG_], d_b2[CG_];
__device__ float d_ps1[C_ * B_], d_pq1[C_ * B_];
__device__ float d_ps2[CG_ * B_], d_pq2[CG_ * B_];
__device__ float d_ocat[B_ * CCAT_ * HW_];   // g[0:64], theta[64:96], phi[96:128] at full res
__device__ float d_gx[B_ * CG_ * NP_];
__device__ float d_phix[B_ * CI_ * NP_];
__device__ float d_S[B_ * CI_ * CG_];
__device__ float d_y[B_ * CG_ * HW_];

// ---------------- concat weights/bias once ----------------
__global__ void k_prep_wcat(const float* __restrict__ w_g, const float* __restrict__ b_g,
                            const float* __restrict__ w_t, const float* __restrict__ b_t,
                            const float* __restrict__ w_p, const float* __restrict__ b_p) {
    int idx = blockIdx.x * blockDim.x + threadIdx.x;
    if (idx >= CCAT_ * C_) return;
    int row = idx / C_, k = idx % C_;
    float v;
    if (row < 64)       v = w_g[row * C_ + k];
    else if (row < 96)  v = w_t[(row - 64) * C_ + k];
    else                v = w_p[(row - 96) * C_ + k];
    d_wcat[idx] = v;
    if (k == 0)
        d_bcat[row] = (row < 64) ? b_g[row] : (row < 96 ? b_t[row - 64] : b_p[row - 96]);
}

// ---------------- BN1 stats: per (channel, batch) partial sums ----------------
__global__ void k_bn1_partial(const float* __restrict__ x) {
    int c = blockIdx.x, b = blockIdx.y;
    const float4* p = (const float4*)(x + ((size_t)(b * C_ + c)) * HW_);
    float s = 0.f, q = 0.f;
    for (int i = threadIdx.x; i < HW_ / 4; i += blockDim.x) {
        float4 v = p[i];
        s += v.x + v.y + v.z + v.w;
        q += v.x * v.x + v.y * v.y + v.z * v.z + v.w * v.w;
    }
    __shared__ float ss[8], sq[8];
    for (int o = 16; o > 0; o >>= 1) {
        s += __shfl_down_sync(0xffffffffu, s, o);
        q += __shfl_down_sync(0xffffffffu, q, o);
    }
    int lane = threadIdx.x & 31, wid = threadIdx.x >> 5;
    if (lane == 0) { ss[wid] = s; sq[wid] = q; }
    __syncthreads();
    if (threadIdx.x == 0) {
        float S = 0.f, Q = 0.f;
        for (int w = 0; w < 8; w++) { S += ss[w]; Q += sq[w]; }
        d_ps1[c * B_ + b] = S;
        d_pq1[c * B_ + b] = Q;
    }
}

__global__ void k_bn1_final(const float* __restrict__ gamma, const float* __restrict__ beta) {
    int c = threadIdx.x;  // launched <<<1, C_>>>
    float s = 0.f, q = 0.f;
    for (int b = 0; b < B_; b++) { s += d_ps1[c * B_ + b]; q += d_pq1[c * B_ + b]; }
    const float invN = 1.f / (float)(B_ * HW_);
    float mean = s * invN;
    float var = q * invN - mean * mean;
    float inv = rsqrtf(var + 1e-5f);
    d_a1[c] = gamma[c] * inv;
    d_b1[c] = beta[c] - mean * gamma[c] * inv;
}

// ---------------- fused BN1+ReLU + concat 1x1 conv: (128x256)@(256x3136) per batch ----------------
__global__ void __launch_bounds__(256) k_conv_cat(const float* __restrict__ x) {
    const int b  = blockIdx.y;
    const int n0 = blockIdx.x * 128;
    __shared__ float As[16][128];   // [k][m] = Wcat[m][k0+k]
    __shared__ float Bs[16][132];   // [k][n] = relu(a1*x + b1)
    float acc[8][8];
#pragma unroll
    for (int i = 0; i < 8; i++)
#pragma unroll
        for (int j = 0; j < 8; j++) acc[i][j] = 0.f;
    const int tid = threadIdx.x;
    const int tx = tid & 15, ty = tid >> 4;

    for (int k0 = 0; k0 < C_; k0 += 16) {
#pragma unroll
        for (int i = 0; i < 2; i++) {
            int idx = tid + i * 256;          // 0..511
            int m = idx >> 2;                 // 0..127
            int k4 = (idx & 3) << 2;          // 0,4,8,12
            float4 v = *(const float4*)(d_wcat + m * C_ + k0 + k4);
            As[k4 + 0][m] = v.x; As[k4 + 1][m] = v.y;
            As[k4 + 2][m] = v.z; As[k4 + 3][m] = v.w;
        }
#pragma unroll
        for (int i = 0; i < 2; i++) {
            int idx = tid + i * 256;          // 0..511
            int k = idx >> 5;                 // 0..15
            int n4 = (idx & 31) << 2;         // 0..124
            int c = k0 + k;
            int hw = n0 + n4;
            float4 v = make_float4(0.f, 0.f, 0.f, 0.f);
            if (hw < HW_)  // HW_ % 4 == 0 and n0,n4 multiples of 4 -> full vector valid
                v = *(const float4*)(x + ((size_t)(b * C_ + c)) * HW_ + hw);
            float a = d_a1[c], bb = d_b1[c];
            v.x = fmaxf(fmaf(a, v.x, bb), 0.f);
            v.y = fmaxf(fmaf(a, v.y, bb), 0.f);
            v.z = fmaxf(fmaf(a, v.z, bb), 0.f);
            v.w = fmaxf(fmaf(a, v.w, bb), 0.f);
            *(float4*)(&Bs[k][n4]) = v;
        }
        __syncthreads();
#pragma unroll 4
        for (int k = 0; k < 16; k++) {
            float av[8], bv[8];
#pragma unroll
            for (int i = 0; i < 8; i++) av[i] = As[k][ty * 8 + i];
#pragma unroll
            for (int j = 0; j < 8; j++) bv[j] = Bs[k][tx * 8 + j];
#pragma unroll
            for (int i = 0; i < 8; i++)
#pragma unroll
                for (int j = 0; j < 8; j++)
                    acc[i][j] = fmaf(av[i], bv[j], acc[i][j]);
        }
        __syncthreads();
    }
#pragma unroll
    for (int i = 0; i < 8; i++) {
        int m = ty * 8 + i;
        float bias = d_bcat[m];
#pragma unroll
        for (int j4 = 0; j4 < 8; j4 += 4) {
            int n = n0 + tx * 8 + j4;
            if (n < HW_) {
                float4 v;
                v.x = acc[i][j4 + 0] + bias;
                v.y = acc[i][j4 + 1] + bias;
                v.z = acc[i][j4 + 2] + bias;
                v.w = acc[i][j4 + 3] + bias;
                *(float4*)(d_ocat + ((size_t)(b * CCAT_ + m)) * HW_ + n) = v;
            }
        }
    }
}

// ---------------- 2x2 maxpool of g and phi channels ----------------
__global__ void k_pool() {
    int idx = blockIdx.x * blockDim.x + threadIdx.x;
    if (idx >= B_ * 96 * NP_) return;
    int pos = idx % NP_;
    int t = idx / NP_;
    int u = t % 96;
    int b = t / 96;
    int i = pos / WP_, j = pos % WP_;
    int c = (u < 64) ? u : (u + 32);   // g: 0..63, phi: 96..127
    const float* base = d_ocat + ((size_t)(b * CCAT_ + c)) * HW_;
    int h0 = 2 * i, w0 = 2 * j;
    float m0 = fmaxf(base[h0 * Wim_ + w0], base[h0 * Wim_ + w0 + 1]);
    float m1 = fmaxf(base[(h0 + 1) * Wim_ + w0], base[(h0 + 1) * Wim_ + w0 + 1]);
    float m = fmaxf(m0, m1);
    if (u < 64) d_gx[(b * CG_ + u) * NP_ + pos] = m;
    else        d_phix[(b * CI_ + (u - 64)) * NP_ + pos] = m;
}

// ---------------- S[b] = phi[b] @ g[b]^T / Np  (32x64, K=784) ----------------
__global__ void __launch_bounds__(256) k_S() {
    const int b = blockIdx.x;
    __shared__ float phs[CI_][116];
    __shared__ float gs[CG_][116];
    float acc[8];
#pragma unroll
    for (int r = 0; r < 8; r++) acc[r] = 0.f;
    const int tid = threadIdx.x;
    const int ii = tid >> 3;          // 0..31
    const int cg_lane = tid & 7;      // outputs cg = cg_lane + 8*j

    for (int m0 = 0; m0 < NP_; m0 += 112) {
        for (int i = tid; i < CI_ * 112; i += 256) {
            int r = i / 112, mm = i % 112;
            phs[r][mm] = d_phix[(b * CI_ + r) * NP_ + m0 + mm];
        }
        for (int i = tid; i < CG_ * 112; i += 256) {
            int r = i / 112, mm = i % 112;
            gs[r][mm] = d_gx[(b * CG_ + r) * NP_ + m0 + mm];
        }
        __syncthreads();
        for (int mm4 = 0; mm4 < 112; mm4 += 4) {
            float4 pv = *(const float4*)(&phs[ii][mm4]);
#pragma unroll
            for (int j = 0; j < 8; j++) {
                float4 gv = *(const float4*)(&gs[cg_lane + 8 * j][mm4]);
                acc[j] = fmaf(pv.x, gv.x, acc[j]);
                acc[j] = fmaf(pv.y, gv.y, acc[j]);
                acc[j] = fmaf(pv.z, gv.z, acc[j]);
                acc[j] = fmaf(pv.w, gv.w, acc[j]);
            }
        }
        __syncthreads();
    }
#pragma unroll
    for (int j = 0; j < 8; j++)
        d_S[b * CI_ * CG_ + ii * CG_ + cg_lane + 8 * j] = acc[j] * (1.f / (float)NP_);
}

// ---------------- y[b,:,hw] = S[b]^T @ theta[b,:,hw] ----------------
__global__ void __launch_bounds__(256) k_y() {
    const int b = blockIdx.y;
    const int hw = blockIdx.x * 256 + threadIdx.x;
    __shared__ float Ss[CI_ * CG_];
    for (int i = threadIdx.x; i < CI_ * CG_; i += 256) Ss[i] = d_S[b * CI_ * CG_ + i];
    __syncthreads();
    if (hw >= HW_) return;
    float acc[CG_];
#pragma unroll
    for (int cg = 0; cg < CG_; cg++) acc[cg] = 0.f;
#pragma unroll 4
    for (int i = 0; i < CI_; i++) {
        float t = d_ocat[((size_t)(b * CCAT_ + 64 + i)) * HW_ + hw];
#pragma unroll
        for (int cg = 0; cg < CG_; cg++)
            acc[cg] = fmaf(t, Ss[i * CG_ + cg], acc[cg]);
    }
#pragma unroll
    for (int cg = 0; cg < CG_; cg++)
        d_y[((size_t)(b * CG_ + cg)) * HW_ + hw] = acc[cg];
}

// ---------------- BN2 stats on y ----------------
__global__ void k_bn2_partial() {
    int c = blockIdx.x, b = blockIdx.y;
    const float4* p = (const float4*)(d_y + ((size_t)(b * CG_ + c)) * HW_);
    float s = 0.f, q = 0.f;
    for (int i = threadIdx.x; i < HW_ / 4; i += blockDim.x) {
        float4 v = p[i];
        s += v.x + v.y + v.z + v.w;
        q += v.x * v.x + v.y * v.y + v.z * v.z + v.w * v.w;
    }
    __shared__ float ss[8], sq[8];
    for (int o = 16; o > 0; o >>= 1) {
        s += __shfl_down_sync(0xffffffffu, s, o);
        q += __shfl_down_sync(0xffffffffu, q, o);
    }
    int lane = threadIdx.x & 31, wid = threadIdx.x >> 5;
    if (lane == 0) { ss[wid] = s; sq[wid] = q; }
    __syncthreads();
    if (threadIdx.x == 0) {
        float S = 0.f, Q = 0.f;
        for (int w = 0; w < 8; w++) { S += ss[w]; Q += sq[w]; }
        d_ps2[c * B_ + b] = S;
        d_pq2[c * B_ + b] = Q;
    }
}

__global__ void k_bn2_final(const float* __restrict__ gamma, const float* __restrict__ beta) {
    int c = threadIdx.x;  // launched <<<1, CG_>>>
    float s = 0.f, q = 0.f;
    for (int b = 0; b < B_; b++) { s += d_ps2[c * B_ + b]; q += d_pq2[c * B_ + b]; }
    const float invN = 1.f / (float)(B_ * HW_);
    float mean = s * invN;
    float var = q * invN - mean * mean;
    float inv = rsqrtf(var + 1e-5f);
    d_a2[c] = gamma[c] * inv;
    d_b2[c] = beta[c] - mean * gamma[c] * inv;
}

// ---------------- final: out = wz @ relu(bn2(y)) + bz + x ----------------
__global__ void __launch_bounds__(256) k_final(const float* __restrict__ wz,
                                               const float* __restrict__ bz,
                                               const float* __restrict__ x,
                                               float* __restrict__ out) {
    const int b  = blockIdx.z;
    const int m0 = blockIdx.y * 128;
    const int n0 = blockIdx.x * 128;
    __shared__ float As[32][128];   // [k][m] = wz[m0+m][k0+k]
    __shared__ float Bs[32][132];   // [k][n] = relu(a2*y+b2)
    float acc[8][8];
#pragma unroll
    for (int i = 0; i < 8; i++)
#pragma unroll
        for (int j = 0; j < 8; j++) acc[i][j] = 0.f;
    const int tid = threadIdx.x;
    const int tx = tid & 15, ty = tid >> 4;

    for (int k0 = 0; k0 < CG_; k0 += 32) {
#pragma unroll
        for (int i = 0; i < 4; i++) {
            int idx = tid + i * 256;          // 0..1023
            int m = idx >> 3;                 // 0..127
            int k4 = (idx & 7) << 2;          // 0..28
            float4 v = *(const float4*)(wz + (m0 + m) * CG_ + k0 + k4);
            As[k4 + 0][m] = v.x; As[k4 + 1][m] = v.y;
            As[k4 + 2][m] = v.z; As[k4 + 3][m] = v.w;
        }
#pragma unroll
        for (int i = 0; i < 4; i++) {
            int idx = tid + i * 256;          // 0..1023
            int k = idx >> 5;                 // 0..31
            int n4 = (idx & 31) << 2;
            int c = k0 + k;
            int hw = n0 + n4;
            float4 v = make_float4(0.f, 0.f, 0.f, 0.f);
            if (hw < HW_)
                v = *(const float4*)(d_y + ((size_t)(b * CG_ + c)) * HW_ + hw);
            float a = d_a2[c], bb = d_b2[c];
            v.x = fmaxf(fmaf(a, v.x, bb), 0.f);
            v.y = fmaxf(fmaf(a, v.y, bb), 0.f);
            v.z = fmaxf(fmaf(a, v.z, bb), 0.f);
            v.w = fmaxf(fmaf(a, v.w, bb), 0.f);
            *(float4*)(&Bs[k][n4]) = v;
        }
        __syncthreads();
#pragma unroll 4
        for (int k = 0; k < 32; k++) {
            float av[8], bv[8];
#pragma unroll
            for (int i = 0; i < 8; i++) av[i] = As[k][ty * 8 + i];
#pragma unroll
            for (int j = 0; j < 8; j++) bv[j] = Bs[k][tx * 8 + j];
#pragma unroll
            for (int i = 0; i < 8; i++)
#pragma unroll
                for (int j = 0; j < 8; j++)
                    acc[i][j] = fmaf(av[i], bv[j], acc[i][j]);
        }
        __syncthreads();
    }
#pragma unroll
    for (int i = 0; i < 8; i++) {
        int m = m0 + ty * 8 + i;
        float bias = bz[m];
#pragma unroll
        for (int j4 = 0; j4 < 8; j4 += 4) {
            int n = n0 + tx * 8 + j4;
            if (n < HW_) {
                size_t off = ((size_t)(b * C_ + m)) * HW_ + n;
                float4 xi = *(const float4*)(x + off);
                float4 v;
                v.x = acc[i][j4 + 0] + bias + xi.x;
                v.y = acc[i][j4 + 1] + bias + xi.y;
                v.z = acc[i][j4 + 2] + bias + xi.z;
                v.w = acc[i][j4 + 3] + bias + xi.w;
                *(float4*)(out + off) = v;
            }
        }
    }
}

// ---------------- launch ----------------
extern "C" void kernel_launch(void* const* d_in, const int* in_sizes, int n_in,
                              void* d_out, int out_size) {
    const float* x   = (const float*)d_in[0];
    const float* g1  = (const float*)d_in[1];
    const float* be1 = (const float*)d_in[2];
    const float* w_g = (const float*)d_in[3];
    const float* b_g = (const float*)d_in[4];
    const float* w_t = (const float*)d_in[5];
    const float* b_t = (const float*)d_in[6];
    const float* w_p = (const float*)d_in[7];
    const float* b_p = (const float*)d_in[8];
    const float* g2  = (const float*)d_in[9];
    const float* be2 = (const float*)d_in[10];
    const float* wz  = (const float*)d_in[11];
    const float* bz  = (const float*)d_in[12];
    float* out = (float*)d_out;

    k_prep_wcat<<<128, 256>>>(w_g, b_g, w_t, b_t, w_p, b_p);
    k_bn1_partial<<<dim3(C_, B_), 256>>>(x);
    k_bn1_final<<<1, C_>>>(g1, be1);
    k_conv_cat<<<dim3(25, B_), 256>>>(x);
    k_pool<<<(B_ * 96 * NP_ + 255) / 256, 256>>>();
    k_S<<<B_, 256>>>();
    k_y<<<dim3(13, B_), 256>>>();
    k_bn2_partial<<<dim3(CG_, B_), 256>>>();
    k_bn2_final<<<1, CG_>>>(g2, be2);
    k_final<<<dim3(25, 2, B_), 256>>>(wz, bz, x, out);
}

// round 2
// speedup vs baseline: 1.2304x; 1.2304x over previous
#include <cuda_runtime.h>

#define B_    16
#define C_    256
#define HW_   3136
#define Wim_  56
#define CI_   32
#define CG_   64
#define NP_   784
#define WP_   28
#define CCAT_ 128

typedef unsigned long long u64;

// packed f32x2 FMA: d = a*b + d (2 fp32 FMAs per instruction)
#define FMA2(d, a, b) asm("fma.rn.f32x2 %0, %1, %2, %0;" : "+l"(d) : "l"(a), "l"(b))
// duplicate a float into both halves of a packed f32x2
#define DUP2(d, s)    asm("mov.b64 %0, {%1, %1};" : "=l"(d) : "f"(s))

// ---------------- scratch (static device globals; no allocation) ----------------
__device__ float d_wcat[CCAT_ * C_];
__device__ float d_bcat[CCAT_];
__device__ float d_a1[C_], d_b1[C_];
__device__ float d_a2[CG_], d_b2[CG_];
__device__ float d_ps1[C_ * B_], d_pq1[C_ * B_];
__device__ float d_ps2[CG_ * B_], d_pq2[CG_ * B_];
__device__ float d_ocat[B_ * CCAT_ * HW_];   // g[0:64], theta[64:96], phi[96:128]
__device__ float d_gx[B_ * CG_ * NP_];
__device__ float d_phix[B_ * CI_ * NP_];
__device__ float d_Sp[B_ * 7 * CI_ * CG_];
__device__ float d_S[B_ * CI_ * CG_];
__device__ float d_y[B_ * CG_ * HW_];

// ---------------- concat weights/bias once ----------------
__global__ void k_prep_wcat(const float* __restrict__ w_g, const float* __restrict__ b_g,
                            const float* __restrict__ w_t, const float* __restrict__ b_t,
                            const float* __restrict__ w_p, const float* __restrict__ b_p) {
    int idx = blockIdx.x * blockDim.x + threadIdx.x;
    if (idx >= CCAT_ * C_) return;
    int row = idx / C_, k = idx % C_;
    float v;
    if (row < 64)       v = w_g[row * C_ + k];
    else if (row < 96)  v = w_t[(row - 64) * C_ + k];
    else                v = w_p[(row - 96) * C_ + k];
    d_wcat[idx] = v;
    if (k == 0)
        d_bcat[row] = (row < 64) ? b_g[row] : (row < 96 ? b_t[row - 64] : b_p[row - 96]);
}

// ---------------- BN1 stats ----------------
__global__ void k_bn1_partial(const float* __restrict__ x) {
    int c = blockIdx.x, b = blockIdx.y;
    const float4* p = (const float4*)(x + ((size_t)(b * C_ + c)) * HW_);
    float s = 0.f, q = 0.f;
    for (int i = threadIdx.x; i < HW_ / 4; i += blockDim.x) {
        float4 v = p[i];
        s += v.x + v.y + v.z + v.w;
        q += v.x * v.x + v.y * v.y + v.z * v.z + v.w * v.w;
    }
    __shared__ float ss[8], sq[8];
    for (int o = 16; o > 0; o >>= 1) {
        s += __shfl_down_sync(0xffffffffu, s, o);
        q += __shfl_down_sync(0xffffffffu, q, o);
    }
    int lane = threadIdx.x & 31, wid = threadIdx.x >> 5;
    if (lane == 0) { ss[wid] = s; sq[wid] = q; }
    __syncthreads();
    if (threadIdx.x == 0) {
        float S = 0.f, Q = 0.f;
        for (int w = 0; w < 8; w++) { S += ss[w]; Q += sq[w]; }
        d_ps1[c * B_ + b] = S;
        d_pq1[c * B_ + b] = Q;
    }
}

__global__ void k_bn1_final(const float* __restrict__ gamma, const float* __restrict__ beta) {
    int c = threadIdx.x;
    float s = 0.f, q = 0.f;
    for (int b = 0; b < B_; b++) { s += d_ps1[c * B_ + b]; q += d_pq1[c * B_ + b]; }
    const float invN = 1.f / (float)(B_ * HW_);
    float mean = s * invN;
    float var = q * invN - mean * mean;
    float inv = rsqrtf(var + 1e-5f);
    d_a1[c] = gamma[c] * inv;
    d_b1[c] = beta[c] - mean * gamma[c] * inv;
}

// ---------------- fused BN1+ReLU + concat conv, packed f32x2 microkernel ----------------
__global__ void __launch_bounds__(256) k_conv_cat(const float* __restrict__ x) {
    const int b  = blockIdx.y;
    const int n0 = blockIdx.x * 128;
    __shared__ float As[16][128];   // [k][m]
    __shared__ float Bs[16][132];   // [k][n]
    // acc2[i2][j]: packed pair over m = (ty*8+2*i2, ty*8+2*i2+1), column n = tx*8+j
    u64 acc2[4][8];
#pragma unroll
    for (int i = 0; i < 4; i++)
#pragma unroll
        for (int j = 0; j < 8; j++) acc2[i][j] = 0ull;
    const int tid = threadIdx.x;
    const int tx = tid & 15, ty = tid >> 4;

    for (int k0 = 0; k0 < C_; k0 += 16) {
#pragma unroll
        for (int i = 0; i < 2; i++) {
            int idx = tid + i * 256;
            int m = idx >> 2;
            int k4 = (idx & 3) << 2;
            float4 v = *(const float4*)(d_wcat + m * C_ + k0 + k4);
            As[k4 + 0][m] = v.x; As[k4 + 1][m] = v.y;
            As[k4 + 2][m] = v.z; As[k4 + 3][m] = v.w;
        }
#pragma unroll
        for (int i = 0; i < 2; i++) {
            int idx = tid + i * 256;
            int k = idx >> 5;
            int n4 = (idx & 31) << 2;
            int c = k0 + k;
            int hw = n0 + n4;
            float4 v = make_float4(0.f, 0.f, 0.f, 0.f);
            if (hw < HW_)
                v = *(const float4*)(x + ((size_t)(b * C_ + c)) * HW_ + hw);
            float a = d_a1[c], bb = d_b1[c];
            v.x = fmaxf(fmaf(a, v.x, bb), 0.f);
            v.y = fmaxf(fmaf(a, v.y, bb), 0.f);
            v.z = fmaxf(fmaf(a, v.z, bb), 0.f);
            v.w = fmaxf(fmaf(a, v.w, bb), 0.f);
            *(float4*)(&Bs[k][n4]) = v;
        }
        __syncthreads();
#pragma unroll
        for (int k = 0; k < 16; k++) {
            // a pairs loaded packed straight from shared (m-consecutive)
            ulonglong2 pa0 = *(const ulonglong2*)(&As[k][ty * 8]);
            ulonglong2 pa1 = *((const ulonglong2*)(&As[k][ty * 8]) + 1);
            u64 av2[4] = {pa0.x, pa0.y, pa1.x, pa1.y};
            float4 bq0 = *(const float4*)(&Bs[k][tx * 8]);
            float4 bq1 = *((const float4*)(&Bs[k][tx * 8]) + 1);
            u64 bd[8];
            DUP2(bd[0], bq0.x); DUP2(bd[1], bq0.y); DUP2(bd[2], bq0.z); DUP2(bd[3], bq0.w);
            DUP2(bd[4], bq1.x); DUP2(bd[5], bq1.y); DUP2(bd[6], bq1.z); DUP2(bd[7], bq1.w);
#pragma unroll
            for (int j = 0; j < 8; j++)
#pragma unroll
                for (int i2 = 0; i2 < 4; i2++)
                    FMA2(acc2[i2][j], av2[i2], bd[j]);
        }
        __syncthreads();
    }
#pragma unroll
    for (int i2 = 0; i2 < 4; i2++) {
#pragma unroll
        for (int half = 0; half < 2; half++) {
            int m = ty * 8 + i2 * 2 + half;
            float bias = d_bcat[m];
            float r[8];
#pragma unroll
            for (int j = 0; j < 8; j++) {
                float2 p = *(const float2*)(&acc2[i2][j]);
                r[j] = (half == 0 ? p.x : p.y) + bias;
            }
#pragma unroll
            for (int j4 = 0; j4 < 8; j4 += 4) {
                int n = n0 + tx * 8 + j4;
                if (n < HW_) {
                    float4 v = make_float4(r[j4], r[j4 + 1], r[j4 + 2], r[j4 + 3]);
                    *(float4*)(d_ocat + ((size_t)(b * CCAT_ + m)) * HW_ + n) = v;
                }
            }
        }
    }
}

// ---------------- 2x2 maxpool of g and phi channels ----------------
__global__ void k_pool() {
    int idx = blockIdx.x * blockDim.x + threadIdx.x;
    if (idx >= B_ * 96 * NP_) return;
    int pos = idx % NP_;
    int t = idx / NP_;
    int u = t % 96;
    int b = t / 96;
    int i = pos / WP_, j = pos % WP_;
    int c = (u < 64) ? u : (u + 32);
    const float* base = d_ocat + ((size_t)(b * CCAT_ + c)) * HW_;
    int h0 = 2 * i, w0 = 2 * j;
    float m0 = fmaxf(base[h0 * Wim_ + w0], base[h0 * Wim_ + w0 + 1]);
    float m1 = fmaxf(base[(h0 + 1) * Wim_ + w0], base[(h0 + 1) * Wim_ + w0 + 1]);
    float m = fmaxf(m0, m1);
    if (u < 64) d_gx[(b * CG_ + u) * NP_ + pos] = m;
    else        d_phix[(b * CI_ + (u - 64)) * NP_ + pos] = m;
}

// ---------------- S partials: per (b, chunk) 32x64 over 112 k-positions ----------------
__global__ void __launch_bounds__(256) k_S_part() {
    const int b = blockIdx.x;
    const int ch = blockIdx.y;
    const int m0 = ch * 112;
    __shared__ float phs[CI_][116];
    __shared__ float gs[CG_][116];
    float acc[8];
#pragma unroll
    for (int r = 0; r < 8; r++) acc[r] = 0.f;
    const int tid = threadIdx.x;
    const int ii = tid >> 3;
    const int cg_lane = tid & 7;

    for (int i = tid; i < CI_ * 112; i += 256) {
        int r = i / 112, mm = i % 112;
        phs[r][mm] = d_phix[(b * CI_ + r) * NP_ + m0 + mm];
    }
    for (int i = tid; i < CG_ * 112; i += 256) {
        int r = i / 112, mm = i % 112;
        gs[r][mm] = d_gx[(b * CG_ + r) * NP_ + m0 + mm];
    }
    __syncthreads();
    for (int mm4 = 0; mm4 < 112; mm4 += 4) {
        float4 pv = *(const float4*)(&phs[ii][mm4]);
#pragma unroll
        for (int j = 0; j < 8; j++) {
            float4 gv = *(const float4*)(&gs[cg_lane + 8 * j][mm4]);
            acc[j] = fmaf(pv.x, gv.x, acc[j]);
            acc[j] = fmaf(pv.y, gv.y, acc[j]);
            acc[j] = fmaf(pv.z, gv.z, acc[j]);
            acc[j] = fmaf(pv.w, gv.w, acc[j]);
        }
    }
#pragma unroll
    for (int j = 0; j < 8; j++)
        d_Sp[((b * 7 + ch) * CI_ + ii) * CG_ + cg_lane + 8 * j] = acc[j];
}

__global__ void k_S_red() {
    const int b = blockIdx.x;
    for (int i = threadIdx.x; i < CI_ * CG_; i += blockDim.x) {
        float s = 0.f;
        for (int ch = 0; ch < 7; ch++)
            s += d_Sp[((b * 7 + ch) * CI_) * CG_ + i];
        d_S[b * CI_ * CG_ + i] = s * (1.f / (float)NP_);
    }
}

// ---------------- y[b,:,hw] = S[b]^T @ theta[b,:,hw], packed f32x2 ----------------
__global__ void __launch_bounds__(256) k_y() {
    const int b = blockIdx.y;
    const int hw = blockIdx.x * 256 + threadIdx.x;
    __shared__ float Ss[CI_ * CG_];
    for (int i = threadIdx.x; i < CI_ * CG_; i += 256) Ss[i] = d_S[b * CI_ * CG_ + i];
    __syncthreads();
    if (hw >= HW_) return;
    u64 acc2[CG_ / 2];
#pragma unroll
    for (int c2 = 0; c2 < CG_ / 2; c2++) acc2[c2] = 0ull;
    const u64* Ss2 = (const u64*)Ss;
#pragma unroll 4
    for (int i = 0; i < CI_; i++) {
        float t = d_ocat[((size_t)(b * CCAT_ + 64 + i)) * HW_ + hw];
        u64 td; DUP2(td, t);
#pragma unroll
        for (int c2 = 0; c2 < CG_ / 2; c2++)
            FMA2(acc2[c2], td, Ss2[i * (CG_ / 2) + c2]);
    }
#pragma unroll
    for (int c2 = 0; c2 < CG_ / 2; c2++) {
        float2 p = *(const float2*)(&acc2[c2]);
        d_y[((size_t)(b * CG_ + 2 * c2)) * HW_ + hw] = p.x;
        d_y[((size_t)(b * CG_ + 2 * c2 + 1)) * HW_ + hw] = p.y;
    }
}

// ---------------- BN2 stats on y ----------------
__global__ void k_bn2_partial() {
    int c = blockIdx.x, b = blockIdx.y;
    const float4* p = (const float4*)(d_y + ((size_t)(b * CG_ + c)) * HW_);
    float s = 0.f, q = 0.f;
    for (int i = threadIdx.x; i < HW_ / 4; i += blockDim.x) {
        float4 v = p[i];
        s += v.x + v.y + v.z + v.w;
        q += v.x * v.x + v.y * v.y + v.z * v.z + v.w * v.w;
    }
    __shared__ float ss[8], sq[8];
    for (int o = 16; o > 0; o >>= 1) {
        s += __shfl_down_sync(0xffffffffu, s, o);
        q += __shfl_down_sync(0xffffffffu, q, o);
    }
    int lane = threadIdx.x & 31, wid = threadIdx.x >> 5;
    if (lane == 0) { ss[wid] = s; sq[wid] = q; }
    __syncthreads();
    if (threadIdx.x == 0) {
        float S = 0.f, Q = 0.f;
        for (int w = 0; w < 8; w++) { S += ss[w]; Q += sq[w]; }
        d_ps2[c * B_ + b] = S;
        d_pq2[c * B_ + b] = Q;
    }
}

__global__ void k_bn2_final(const float* __restrict__ gamma, const float* __restrict__ beta) {
    int c = threadIdx.x;
    float s = 0.f, q = 0.f;
    for (int b = 0; b < B_; b++) { s += d_ps2[c * B_ + b]; q += d_pq2[c * B_ + b]; }
    const float invN = 1.f / (float)(B_ * HW_);
    float mean = s * invN;
    float var = q * invN - mean * mean;
    float inv = rsqrtf(var + 1e-5f);
    d_a2[c] = gamma[c] * inv;
    d_b2[c] = beta[c] - mean * gamma[c] * inv;
}

// ---------------- final: out = wz @ relu(bn2(y)) + bz + x, packed f32x2 ----------------
__global__ void __launch_bounds__(256) k_final(const float* __restrict__ wz,
                                               const float* __restrict__ bz,
                                               const float* __restrict__ x,
                                               float* __restrict__ out) {
    const int b  = blockIdx.z;
    const int m0 = blockIdx.y * 128;
    const int n0 = blockIdx.x * 128;
    __shared__ float As[32][128];
    __shared__ float Bs[32][132];
    u64 acc2[4][8];
#pragma unroll
    for (int i = 0; i < 4; i++)
#pragma unroll
        for (int j = 0; j < 8; j++) acc2[i][j] = 0ull;
    const int tid = threadIdx.x;
    const int tx = tid & 15, ty = tid >> 4;

    for (int k0 = 0; k0 < CG_; k0 += 32) {
#pragma unroll
        for (int i = 0; i < 4; i++) {
            int idx = tid + i * 256;
            int m = idx >> 3;
            int k4 = (idx & 7) << 2;
            float4 v = *(const float4*)(wz + (m0 + m) * CG_ + k0 + k4);
            As[k4 + 0][m] = v.x; As[k4 + 1][m] = v.y;
            As[k4 + 2][m] = v.z; As[k4 + 3][m] = v.w;
        }
#pragma unroll
        for (int i = 0; i < 4; i++) {
            int idx = tid + i * 256;
            int k = idx >> 5;
            int n4 = (idx & 31) << 2;
            int c = k0 + k;
            int hw = n0 + n4;
            float4 v = make_float4(0.f, 0.f, 0.f, 0.f);
            if (hw < HW_)
                v = *(const float4*)(d_y + ((size_t)(b * CG_ + c)) * HW_ + hw);
            float a = d_a2[c], bb = d_b2[c];
            v.x = fmaxf(fmaf(a, v.x, bb), 0.f);
            v.y = fmaxf(fmaf(a, v.y, bb), 0.f);
            v.z = fmaxf(fmaf(a, v.z, bb), 0.f);
            v.w = fmaxf(fmaf(a, v.w, bb), 0.f);
            *(float4*)(&Bs[k][n4]) = v;
        }
        __syncthreads();
#pragma unroll
        for (int k = 0; k < 32; k++) {
            ulonglong2 pa0 = *(const ulonglong2*)(&As[k][ty * 8]);
            ulonglong2 pa1 = *((const ulonglong2*)(&As[k][ty * 8]) + 1);
            u64 av2[4] = {pa0.x, pa0.y, pa1.x, pa1.y};
            float4 bq0 = *(const float4*)(&Bs[k][tx * 8]);
            float4 bq1 = *((const float4*)(&Bs[k][tx * 8]) + 1);
            u64 bd[8];
            DUP2(bd[0], bq0.x); DUP2(bd[1], bq0.y); DUP2(bd[2], bq0.z); DUP2(bd[3], bq0.w);
            DUP2(bd[4], bq1.x); DUP2(bd[5], bq1.y); DUP2(bd[6], bq1.z); DUP2(bd[7], bq1.w);
#pragma unroll
            for (int j = 0; j < 8; j++)
#pragma unroll
                for (int i2 = 0; i2 < 4; i2++)
                    FMA2(acc2[i2][j], av2[i2], bd[j]);
        }
        __syncthreads();
    }
#pragma unroll
    for (int i2 = 0; i2 < 4; i2++) {
#pragma unroll
        for (int half = 0; half < 2; half++) {
            int m = m0 + ty * 8 + i2 * 2 + half;
            float bias = bz[m];
            float r[8];
#pragma unroll
            for (int j = 0; j < 8; j++) {
                float2 p = *(const float2*)(&acc2[i2][j]);
                r[j] = (half == 0 ? p.x : p.y) + bias;
            }
#pragma unroll
            for (int j4 = 0; j4 < 8; j4 += 4) {
                int n = n0 + tx * 8 + j4;
                if (n < HW_) {
                    size_t off = ((size_t)(b * C_ + m)) * HW_ + n;
                    float4 xi = *(const float4*)(x + off);
                    float4 v = make_float4(r[j4] + xi.x, r[j4 + 1] + xi.y,
                                           r[j4 + 2] + xi.z, r[j4 + 3] + xi.w);
                    *(float4*)(out + off) = v;
                }
            }
        }
    }
}

// ---------------- launch ----------------
extern "C" void kernel_launch(void* const* d_in, const int* in_sizes, int n_in,
                              void* d_out, int out_size) {
    const float* x   = (const float*)d_in[0];
    const float* g1  = (const float*)d_in[1];
    const float* be1 = (const float*)d_in[2];
    const float* w_g = (const float*)d_in[3];
    const float* b_g = (const float*)d_in[4];
    const float* w_t = (const float*)d_in[5];
    const float* b_t = (const float*)d_in[6];
    const float* w_p = (const float*)d_in[7];
    const float* b_p = (const float*)d_in[8];
    const float* g2  = (const float*)d_in[9];
    const float* be2 = (const float*)d_in[10];
    const float* wz  = (const float*)d_in[11];
    const float* bz  = (const float*)d_in[12];
    float* out = (float*)d_out;

    k_prep_wcat<<<128, 256>>>(w_g, b_g, w_t, b_t, w_p, b_p);
    k_bn1_partial<<<dim3(C_, B_), 256>>>(x);
    k_bn1_final<<<1, C_>>>(g1, be1);
    k_conv_cat<<<dim3(25, B_), 256>>>(x);
    k_pool<<<(B_ * 96 * NP_ + 255) / 256, 256>>>();
    k_S_part<<<dim3(B_, 7), 256>>>();
    k_S_red<<<B_, 256>>>();
    k_y<<<dim3(13, B_), 256>>>();
    k_bn2_partial<<<dim3(CG_, B_), 256>>>();
    k_bn2_final<<<1, CG_>>>(g2, be2);
    k_final<<<dim3(25, 2, B_), 256>>>(wz, bz, x, out);
}